// round 14
// baseline (speedup 1.0000x reference)
#include <cuda_runtime.h>

#define NB      64
#define NT      1024
#define MAXLAG  256
#define NCHUNK  16
#define NTHR    256

// Scratch (device globals; allocation forbidden). Partials fully overwritten
// each launch. Counters self-reset -> deterministic across graph replays.
// Layout [b][L][chunk]: finalizer reads 16 partials as 4x LDG.128.
__device__ float    g_msd_part[NB][MAXLAG][NCHUNK];
__device__ float    g_per_traj[NB];
__device__ unsigned g_cnt_traj[NB];
__device__ unsigned g_cnt_final;

// lengths declared int64 in the reference but JAX w/o x64 emits int32.
// Little-endian int64 -> every odd 32-bit word is 0; int32 -> word1 >= 512.
__device__ __forceinline__ int read_len(const int* __restrict__ p, int b)
{
    return (p[1] == 0) ? p[2 * b] : p[b];
}

// Release+acquire fetch-add (replaces __threadfence + atomicAdd on the
// finalize chain; pairs with the preceding __syncthreads).
__device__ __forceinline__ unsigned atom_add_acqrel(unsigned* addr, unsigned v)
{
    unsigned old;
    asm volatile("atom.acq_rel.gpu.global.add.u32 %0, [%1], %2;"
                 : "=r"(old) : "l"(addr), "r"(v) : "memory");
    return old;
}

// Single-pass block reduction of a float2 (8 warps / 256 threads).
__device__ __forceinline__ float2 block_sum2_256(float2 v, float2* sbuf)
{
    #pragma unroll
    for (int o = 16; o > 0; o >>= 1) {
        v.x += __shfl_down_sync(0xffffffffu, v.x, o);
        v.y += __shfl_down_sync(0xffffffffu, v.y, o);
    }
    const int warp = threadIdx.x >> 5;
    if ((threadIdx.x & 31) == 0) sbuf[warp] = v;
    __syncthreads();
    if (threadIdx.x < 8) {
        v = sbuf[threadIdx.x];
        #pragma unroll
        for (int o = 4; o > 0; o >>= 1) {
            v.x += __shfl_down_sync(0xffu, v.x, o);
            v.y += __shfl_down_sync(0xffu, v.y, o);
        }
        if (threadIdx.x == 0) sbuf[0] = v;
    }
    __syncthreads();
    return sbuf[0];
}

// ---------------------------------------------------------------------------
// Fused kernel. grid = (NB, NCHUNK), block = 256 (thread t <-> lag L = t+1).
// Phase 1: partial MSD over interleaved positions p = chunk + 16k (the
//          simple R4-style loop: best measured kernel duration of the series;
//          ptxas schedules the LDS/FFMA stream better than manual unrolls).
// Phase 2 (last block per b): per-trajectory log-fit loss, one reduction via
//          the variance identity (denom is closed-form: min(len-1, 256)).
// Phase 3 (last finalizer): mean over trajectories.
// ---------------------------------------------------------------------------
__global__ __launch_bounds__(NTHR) void fused_kernel(
    const float* __restrict__ traj,
    const int*   __restrict__ lengths_raw,
    const float* __restrict__ alpha_pred,
    float*       __restrict__ out)
{
    __shared__ __align__(16) float2 y[NT];
    __shared__ float2   sbuf[8];
    __shared__ unsigned s_flag;

    const int b     = blockIdx.x;
    const int chunk = blockIdx.y;
    const int t     = threadIdx.x;
    const int L     = t + 1;

    // ---- stage trajectory into smem; prefetch scalars -------------------
    {
        const float4* src = reinterpret_cast<const float4*>(traj + (size_t)b * NT * 2);
        float4* dst = reinterpret_cast<float4*>(y);
        #pragma unroll
        for (int i = t; i < NT / 2; i += NTHR)
            dst[i] = src[i];
    }
    const int   len   = read_len(lengths_raw, b);
    const float alpha = alpha_pred[b];          // prefetched for the tail
    __syncthreads();

    const int bound = len - L;                  // valid positions p in [0,bound)

    // ---- Phase 1: MSD partial (simple scalar-float2 loop) ---------------
    float acc = 0.0f;
    #pragma unroll 4
    for (int p = chunk; p < bound; p += NCHUNK) {
        float2 s = y[p];
        float2 e = y[p + L];
        float dx = e.x - s.x;
        float dy = e.y - s.y;
        acc += dx * dx + dy * dy;
    }
    g_msd_part[b][t][chunk] = acc;

    // ---- elect finalizer block for this trajectory (release+acquire) ----
    __syncthreads();                 // all partial STGs of this block issued
    if (t == 0) s_flag = atom_add_acqrel(&g_cnt_traj[b], 1u);
    __syncthreads();
    if (s_flag != NCHUNK - 1) return;            // uniform per block

    // ---- Phase 2: per-trajectory loss (single fused reduction) ----------
    if (t == 0) g_cnt_traj[b] = 0u;              // reset for next replay

    // 16 partials = 4 vector loads
    const float4* part = reinterpret_cast<const float4*>(g_msd_part[b][t]);
    float4 q0 = part[0], q1 = part[1], q2 = part[2], q3 = part[3];
    float msd = ((q0.x + q0.y) + (q0.z + q0.w))
              + ((q1.x + q1.y) + (q1.z + q1.w))
              + ((q2.x + q2.y) + (q2.z + q2.w))
              + ((q3.x + q3.y) + (q3.z + q3.w));
    msd /= fmaxf((float)bound, 1.0f);

    const float log_msd = logf(msd + 1e-8f);
    const float log_lag = logf((float)L);
    const float mask    = (len > L) ? 1.0f : 0.0f;
    const float resid   = (log_msd - alpha * log_lag) * mask;

    // denom = #lags with len > L = min(len-1, MAXLAG), clamped >= 1
    const int   dcnt  = (len - 1 < MAXLAG) ? (len - 1) : MAXLAG;
    const float denom = (float)((dcnt > 1) ? dcnt : 1);

    // per_traj = E[resid^2] - E[resid]^2 over masked lags (variance identity)
    float2 s2 = block_sum2_256(make_float2(resid, resid * resid), sbuf);
    const float intercept = s2.x / denom;
    const float per_traj  = s2.y / denom - intercept * intercept;

    // ---- elect mean block (release+acquire) ------------------------------
    if (t == 0) {
        g_per_traj[b] = per_traj;
        s_flag = atom_add_acqrel(&g_cnt_final, 1u);
    }
    __syncthreads();
    if (s_flag != NB - 1) return;

    // ---- Phase 3: mean over trajectories ---------------------------------
    if (t == 0) g_cnt_final = 0u;                // reset for next replay

    if (t < 64) {
        float v = g_per_traj[t];
        #pragma unroll
        for (int o = 16; o > 0; o >>= 1)
            v += __shfl_down_sync(0xffffffffu, v, o);
        if ((t & 31) == 0) sbuf[t >> 5].x = v;
    }
    __syncthreads();
    if (t == 0) out[0] = (sbuf[0].x + sbuf[1].x) * (1.0f / (float)NB);
}

// ---------------------------------------------------------------------------
extern "C" void kernel_launch(void* const* d_in, const int* in_sizes, int n_in,
                              void* d_out, int out_size)
{
    const float* alpha       = (const float*)d_in[0];   // [64]
    const float* traj        = (const float*)d_in[1];   // [64,1024,2]
    const int*   lengths_raw = (const int*)d_in[2];     // [64] int32 or int64
    float* out = (float*)d_out;

    dim3 grid(NB, NCHUNK);
    fused_kernel<<<grid, NTHR>>>(traj, lengths_raw, alpha, out);
}

// round 16
// speedup vs baseline: 1.1733x; 1.1733x over previous
#include <cuda_runtime.h>

#define NB      64
#define NT      1024
#define MAXLAG  256
#define NPG     16         /* position groups {2g,2g+1} mod 32 */
#define NBY     8          /* blocks per trajectory; 2 groups per block */
#define NTHR    256

// Scratch (device globals; allocation forbidden). Partials fully overwritten
// each launch. Counters self-reset -> deterministic across graph replays.
// Layout [b][pg][lag]; each thread stores its two lags as one float2.
__device__ float    g_msd_part[NB][NPG][MAXLAG];
__device__ float    g_per_traj[NB];
__device__ unsigned g_cnt_traj[NB];
__device__ unsigned g_cnt_final;

// lengths declared int64 in the reference but JAX w/o x64 emits int32.
// Little-endian int64 -> every odd 32-bit word is 0; int32 -> word1 >= 512.
__device__ __forceinline__ int read_len(const int* __restrict__ p, int b)
{
    return (p[1] == 0) ? p[2 * b] : p[b];
}

// Release+acquire fetch-add for the finalize chain.
__device__ __forceinline__ unsigned atom_add_acqrel(unsigned* addr, unsigned v)
{
    unsigned old;
    asm volatile("atom.acq_rel.gpu.global.add.u32 %0, [%1], %2;"
                 : "=r"(old) : "l"(addr), "r"(v) : "memory");
    return old;
}

#define FMA2(acc, s, e) \
    asm("fma.rn.f32x2 %0, %1, %2, %0;" : "+l"(acc) : "l"(s), "l"(e))
#define DIFF2(d, s, e) \
    asm("fma.rn.f32x2 %0, %1, %2, %3;" : "=l"(d) : "l"(s), "l"(NEG1), "l"(e))

// Single-pass block reduction of a float2 (8 warps / 256 threads).
__device__ __forceinline__ float2 block_sum2_256(float2 v, float2* sbuf)
{
    #pragma unroll
    for (int o = 16; o > 0; o >>= 1) {
        v.x += __shfl_down_sync(0xffffffffu, v.x, o);
        v.y += __shfl_down_sync(0xffffffffu, v.y, o);
    }
    const int warp = threadIdx.x >> 5;
    if ((threadIdx.x & 31) == 0) sbuf[warp] = v;
    __syncthreads();
    if (threadIdx.x < 8) {
        v = sbuf[threadIdx.x];
        #pragma unroll
        for (int o = 4; o > 0; o >>= 1) {
            v.x += __shfl_down_sync(0xffu, v.x, o);
            v.y += __shfl_down_sync(0xffu, v.y, o);
        }
        if (threadIdx.x == 0) sbuf[0] = v;
    }
    __syncthreads();
    return sbuf[0];
}

// ---------------------------------------------------------------------------
// Fused kernel, lag-paired. grid = (NB, NBY), block = 256.
// Thread t: u = t & 127 -> lags Lo = 2u+1, Le = 2u+2;
//           pg = (t>>7) + 2*blockIdx.y -> even positions p = 2*pg + 32k,
//           processed as pairs (p, p+1).
// Per 4 (pos,lag) pairs: 3 LDS.128 (1 broadcast s, 2 contiguous e) + 8 FLOP.
// Phase 2 (last block per b): per-trajectory log-fit loss, one reduction.
// Phase 3 (last finalizer): mean over trajectories.
// ---------------------------------------------------------------------------
__global__ __launch_bounds__(NTHR) void fused_kernel(
    const float* __restrict__ traj,
    const int*   __restrict__ lengths_raw,
    const float* __restrict__ alpha_pred,
    float*       __restrict__ out)
{
    __shared__ __align__(16) float2 y[NT];
    __shared__ float2   sbuf[8];
    __shared__ unsigned s_flag;

    const int b  = blockIdx.x;
    const int t  = threadIdx.x;
    const int u  = t & 127;                    // lag-pair id (lane-consecutive)
    const int pg = (t >> 7) + (blockIdx.y << 1);

    // ---- stage trajectory into smem; prefetch scalars -------------------
    {
        const float4* src = reinterpret_cast<const float4*>(traj + (size_t)b * NT * 2);
        float4* dst = reinterpret_cast<float4*>(y);
        #pragma unroll
        for (int i = t; i < NT / 2; i += NTHR)
            dst[i] = src[i];
    }
    const int   len   = read_len(lengths_raw, b);
    const float alpha = alpha_pred[b];
    __syncthreads();

    // lags and their position bounds
    const int Le      = 2 * u + 2;             // even lag (larger)
    const int bound_e = len - Le;              // (p,Le) valid for p < bound_e
    // (p,Lo) valid for p < bound_e + 1

    const ulonglong2*         y128 = reinterpret_cast<const ulonglong2*>(y);
    const unsigned long long* y64  = reinterpret_cast<const unsigned long long*>(y);
    const unsigned long long NEG1 = 0xBF800000BF800000ULL;   // {-1.f,-1.f}

    unsigned long long accO1 = 0ULL, accE1 = 0ULL, accO2 = 0ULL, accE2 = 0ULL;

    int p = 2 * pg;                            // even base position

    // group macro: 4 pairs at even position q:
    //   (q,Lo)<-sv.x,eo.y  (q,Le)<-sv.x,ev.x  (q+1,Lo)<-sv.y,ev.x  (q+1,Le)<-sv.y,ev.y
    #define GROUP(q)                                                        \
    {                                                                       \
        ulonglong2 sv = y128[(q) >> 1];                /* y[q], y[q+1]   */ \
        ulonglong2 eo = y128[((q) >> 1) + u];          /* y[q+2u..2u+1]  */ \
        ulonglong2 ev = y128[((q) >> 1) + u + 1];      /* y[q+2u+2..3]   */ \
        unsigned long long d;                                               \
        DIFF2(d, sv.x, eo.y); FMA2(accO1, d, d);                            \
        DIFF2(d, sv.x, ev.x); FMA2(accE1, d, d);                            \
        DIFF2(d, sv.y, ev.x); FMA2(accO2, d, d);                            \
        DIFF2(d, sv.y, ev.y); FMA2(accE2, d, d);                            \
    }

    // main loop: 2 groups (8 pairs) per body
    for (; p + 33 < bound_e; p += 64) {
        GROUP(p);
        GROUP(p + 32);
    }
    for (; p + 1 < bound_e; p += 32)
        GROUP(p);
    #undef GROUP

    // tails: p+1 >= bound_e; some pairs may remain valid
    if (p < bound_e) {
        // (p,Lo), (p,Le), (p+1,Lo) valid; (p+1,Le) not
        ulonglong2 sv = y128[p >> 1];
        unsigned long long e1 = y64[p + 2 * u + 1];
        unsigned long long e2 = y64[p + 2 * u + 2];
        unsigned long long d;
        DIFF2(d, sv.x, e1); FMA2(accO1, d, d);
        DIFF2(d, sv.x, e2); FMA2(accE1, d, d);
        DIFF2(d, sv.y, e2); FMA2(accO2, d, d);
    } else if (p < bound_e + 1) {
        // p == bound_e: only (p,Lo)
        unsigned long long s = y64[p];
        unsigned long long e = y64[p + 2 * u + 1];
        unsigned long long d;
        DIFF2(d, s, e); FMA2(accO1, d, d);
    }

    // combine accumulator pairs and store both lags as one float2
    {
        unsigned long long ao, ae;
        asm("add.rn.f32x2 %0, %1, %2;" : "=l"(ao) : "l"(accO1), "l"(accO2));
        asm("add.rn.f32x2 %0, %1, %2;" : "=l"(ae) : "l"(accE1), "l"(accE2));
        float ox, oy, ex, ey;
        asm("mov.b64 {%0, %1}, %2;" : "=f"(ox), "=f"(oy) : "l"(ao));
        asm("mov.b64 {%0, %1}, %2;" : "=f"(ex), "=f"(ey) : "l"(ae));
        reinterpret_cast<float2*>(g_msd_part[b][pg])[u] =
            make_float2(ox + oy, ex + ey);     // lag idx 2u, 2u+1 coalesced
    }

    // ---- elect finalizer block for this trajectory (release+acquire) ----
    __syncthreads();
    if (t == 0) s_flag = atom_add_acqrel(&g_cnt_traj[b], 1u);
    __syncthreads();
    if (s_flag != NBY - 1) return;             // uniform per block

    // ---- Phase 2: per-trajectory loss (single fused reduction) ----------
    if (t == 0) g_cnt_traj[b] = 0u;            // reset for next replay

    const int L = t + 1;                       // thread t <-> lag L
    float msd = 0.0f;
    #pragma unroll
    for (int g = 0; g < NPG; g++)
        msd += g_msd_part[b][g][t];            // warp-coalesced per g
    msd /= fmaxf((float)(len - L), 1.0f);

    const float log_msd = logf(msd + 1e-8f);
    const float log_lag = logf((float)L);
    const float mask    = (len > L) ? 1.0f : 0.0f;
    const float resid   = (log_msd - alpha * log_lag) * mask;

    const int   dcnt  = (len - 1 < MAXLAG) ? (len - 1) : MAXLAG;
    const float denom = (float)((dcnt > 1) ? dcnt : 1);

    float2 s2 = block_sum2_256(make_float2(resid, resid * resid), sbuf);
    const float intercept = s2.x / denom;
    const float per_traj  = s2.y / denom - intercept * intercept;

    // ---- elect mean block (release+acquire) ------------------------------
    if (t == 0) {
        g_per_traj[b] = per_traj;
        s_flag = atom_add_acqrel(&g_cnt_final, 1u);
    }
    __syncthreads();
    if (s_flag != NB - 1) return;

    // ---- Phase 3: mean over trajectories ---------------------------------
    if (t == 0) g_cnt_final = 0u;              // reset for next replay

    if (t < 64) {
        float v = g_per_traj[t];
        #pragma unroll
        for (int o = 16; o > 0; o >>= 1)
            v += __shfl_down_sync(0xffffffffu, v, o);
        if ((t & 31) == 0) sbuf[t >> 5].x = v;
    }
    __syncthreads();
    if (t == 0) out[0] = (sbuf[0].x + sbuf[1].x) * (1.0f / (float)NB);
}

// ---------------------------------------------------------------------------
extern "C" void kernel_launch(void* const* d_in, const int* in_sizes, int n_in,
                              void* d_out, int out_size)
{
    const float* alpha       = (const float*)d_in[0];   // [64]
    const float* traj        = (const float*)d_in[1];   // [64,1024,2]
    const int*   lengths_raw = (const int*)d_in[2];     // [64] int32 or int64
    float* out = (float*)d_out;

    dim3 grid(NB, NBY);
    fused_kernel<<<grid, NTHR>>>(traj, lengths_raw, alpha, out);
}